// round 1
// baseline (speedup 1.0000x reference)
#include <cuda_runtime.h>
#include <math.h>

// Problem dims
#define SEQ_LEN 12
#define BATCH   512
#define NG      16
#define GROUP   32
#define HD      128      // H
#define ED      64       // E
#define PRE     512
#define BOTTLE  1024
#define MLPD    1024
#define GATES   (4*HD)   // 512
#define KCAT    (ED+HD)  // 192
#define ROWS_PN (NG*GROUP*GROUP)  // 16384
#define DHK     (HD+BOTTLE)       // 1152

// ---------------- scratch (device globals; no allocation) ----------------
__device__ float g_h[BATCH*HD];
__device__ float g_c[BATCH*HD];
__device__ float g_pos[BATCH*2];
__device__ float g_decin[BATCH*ED];
__device__ float g_acat[BATCH*KCAT];
__device__ float g_Wcat[GATES*KCAT];
__device__ float g_bsum[GATES];
__device__ float g_gates[BATCH*GATES];
__device__ float g_emb[ROWS_PN*ED];
__device__ float g_hW1h[BATCH*PRE];
__device__ float g_X1[ROWS_PN*PRE];
__device__ float g_pool[BATCH*BOTTLE];
__device__ float g_dcat[BATCH*DHK];
__device__ float g_D1[BATCH*MLPD];
__device__ float g_loss;

__device__ __forceinline__ float sigmoidf(float x) { return 1.0f / (1.0f + expf(-x)); }

// ---------------- init: copy state, pack LSTM weights, dec_in0 ----------------
__global__ void init_kernel(const float* __restrict__ hh, const float* __restrict__ ch,
                            const float* __restrict__ last_pos, const float* __restrict__ last_pos_rel,
                            const float* __restrict__ Wih, const float* __restrict__ Whh,
                            const float* __restrict__ bih, const float* __restrict__ bhh,
                            const float* __restrict__ Wse, const float* __restrict__ bse) {
    int idx = blockIdx.x * blockDim.x + threadIdx.x;
    if (idx < BATCH*HD) { g_h[idx] = hh[idx]; g_c[idx] = ch[idx]; }
    if (idx < BATCH*2)  g_pos[idx] = last_pos[idx];
    if (idx < BATCH*ED) {
        int b = idx / ED, e = idx % ED;
        g_decin[idx] = last_pos_rel[b*2] * Wse[e*2] + last_pos_rel[b*2+1] * Wse[e*2+1] + bse[e];
    }
    if (idx < GATES) g_bsum[idx] = bih[idx] + bhh[idx];
    if (idx < GATES*KCAT) {
        int n = idx / KCAT, k = idx % KCAT;
        g_Wcat[idx] = (k < ED) ? Wih[n*ED + k] : Whh[n*HD + (k - ED)];
    }
    if (idx == 0) g_loss = 0.0f;
}

// ---------------- packs ----------------
__global__ void pack_lstm_kernel() {
    int idx = blockIdx.x * blockDim.x + threadIdx.x;
    if (idx >= BATCH*KCAT) return;
    int b = idx / KCAT, k = idx % KCAT;
    g_acat[idx] = (k < ED) ? g_decin[b*ED + k] : g_h[b*HD + (k - ED)];
}

__global__ void pack_dh_kernel() {
    int idx = blockIdx.x * blockDim.x + threadIdx.x;
    if (idx >= BATCH*DHK) return;
    int b = idx / DHK, k = idx % DHK;
    g_dcat[idx] = (k < HD) ? g_h[b*HD + k] : g_pool[b*BOTTLE + (k - HD)];
}

__global__ void zero_pool_kernel() {
    int idx = blockIdx.x * blockDim.x + threadIdx.x;
    if (idx < BATCH*BOTTLE) g_pool[idx] = 0.0f;
}

// ---------------- LSTM elementwise ----------------
__global__ void lstm_elem_kernel() {
    int idx = blockIdx.x * blockDim.x + threadIdx.x;
    if (idx >= BATCH*HD) return;
    int b = idx / HD, j = idx % HD;
    const float* gr = g_gates + b*GATES;
    float ig = gr[j], fg = gr[HD + j], gg = gr[2*HD + j], og = gr[3*HD + j];
    float c = sigmoidf(fg) * g_c[idx] + sigmoidf(ig) * tanhf(gg);
    g_c[idx] = c;
    g_h[idx] = sigmoidf(og) * tanhf(c);
}

// ---------------- rel_pos, curr_pos, pred output, loss accumulation ----------------
// 1 block x 512 threads; deterministic tree reduce for loss.
__global__ void pos_loss_kernel(const float* __restrict__ Wpos, const float* __restrict__ bpos,
                                const float* __restrict__ gt, float* __restrict__ out_pred) {
    int b = threadIdx.x;
    const float* hr = g_h + b*HD;
    float ax = 0.f, ay = 0.f;
    #pragma unroll 8
    for (int k = 0; k < HD; k++) { float hv = hr[k]; ax += hv * Wpos[k]; ay += hv * Wpos[HD + k]; }
    float rx = ax + bpos[0], ry = ay + bpos[1];
    out_pred[b*2]   = rx;
    out_pred[b*2+1] = ry;
    g_pos[b*2]   += rx;
    g_pos[b*2+1] += ry;
    float dx = rx - gt[b*2], dy = ry - gt[b*2+1];
    __shared__ float sd[BATCH];
    sd[b] = dx*dx + dy*dy;
    __syncthreads();
    for (int s = BATCH/2; s > 0; s >>= 1) {
        if (b < s) sd[b] += sd[b + s];
        __syncthreads();
    }
    if (b == 0) g_loss += sd[0] / (float)(BATCH*2);
}

// ---------------- pairwise rel-pos embedding (K=2 handled directly) ----------------
__global__ void emb_kernel(const float* __restrict__ Wp, const float* __restrict__ bp) {
    int idx = blockIdx.x * blockDim.x + threadIdx.x;
    if (idx >= ROWS_PN*ED) return;
    int r = idx >> 6, e = idx & 63;
    int g = r >> 10, i = (r >> 5) & 31, j = r & 31;
    int bi = g*GROUP + i, bj = g*GROUP + j;
    float rx = g_pos[bj*2]   - g_pos[bi*2];
    float ry = g_pos[bj*2+1] - g_pos[bi*2+1];
    g_emb[idx] = rx * Wp[e*2] + ry * Wp[e*2+1] + bp[e];
}

// ---------------- next dec_in from teacher forcing ----------------
__global__ void decin_kernel(const float* __restrict__ gt,
                             const float* __restrict__ Wse, const float* __restrict__ bse) {
    int idx = blockIdx.x * blockDim.x + threadIdx.x;
    if (idx >= BATCH*ED) return;
    int b = idx / ED, e = idx % ED;
    g_decin[idx] = gt[b*2] * Wse[e*2] + gt[b*2+1] * Wse[e*2+1] + bse[e];
}

// ---------------- finish: write loss scalar ----------------
__global__ void finish_kernel(float* __restrict__ out, int out_size) {
    if (out_size > SEQ_LEN*BATCH*2) out[SEQ_LEN*BATCH*2] = g_loss;
}

// ---------------- generic tiled SGEMM: C = A(MxK) * W(NxK)^T, both K-major ----------------
// MODE 0: store acc
// MODE 1: store acc + bias[n]
// MODE 2: store relu(acc + bias[n])
// MODE 3: X1 mode: store relu(acc + bias[n] + aux[(g*32+j)*PRE + n]), row m -> g=m/1024, j=m%32
// MODE 4: X2/pool mode: v = relu(acc + bias[n]); atomicMax into C[(g*32+i)*ldc + n], i=(m/32)%32
template<int MODE>
__global__ void sgemm64(const float* __restrict__ A, int lda,
                        const float* __restrict__ W, int ldw,
                        float* __restrict__ C, int ldc, int K,
                        const float* __restrict__ bias,
                        const float* __restrict__ aux) {
    __shared__ float As[64][17];
    __shared__ float Ws[64][17];
    int tid = threadIdx.x;                 // 256 threads
    int m0 = blockIdx.y * 64, n0 = blockIdx.x * 64;
    int ty = tid >> 4, tx = tid & 15;
    float acc[4][4] = {};

    for (int k0 = 0; k0 < K; k0 += 16) {
        #pragma unroll
        for (int l = tid; l < 64*16; l += 256) {
            int r = l >> 4, c = l & 15;
            As[r][c] = A[(m0 + r) * lda + k0 + c];
            Ws[r][c] = W[(n0 + r) * ldw + k0 + c];
        }
        __syncthreads();
        #pragma unroll
        for (int kk = 0; kk < 16; kk++) {
            float a[4], w[4];
            #pragma unroll
            for (int i = 0; i < 4; i++) { a[i] = As[ty*4 + i][kk]; w[i] = Ws[tx*4 + i][kk]; }
            #pragma unroll
            for (int i = 0; i < 4; i++)
                #pragma unroll
                for (int j = 0; j < 4; j++) acc[i][j] += a[i] * w[j];
        }
        __syncthreads();
    }

    #pragma unroll
    for (int i = 0; i < 4; i++) {
        int m = m0 + ty*4 + i;
        #pragma unroll
        for (int j = 0; j < 4; j++) {
            int n = n0 + tx*4 + j;
            float v = acc[i][j];
            if (MODE == 0) {
                C[m*ldc + n] = v;
            } else if (MODE == 1) {
                C[m*ldc + n] = v + bias[n];
            } else if (MODE == 2) {
                v += bias[n];
                C[m*ldc + n] = fmaxf(v, 0.0f);
            } else if (MODE == 3) {
                int g = m >> 10, jj = m & 31;
                v += bias[n] + aux[(g*GROUP + jj)*PRE + n];
                C[m*ldc + n] = fmaxf(v, 0.0f);
            } else { // MODE 4
                v = fmaxf(v + bias[n], 0.0f);
                int g = m >> 10, ii = (m >> 5) & 31;
                atomicMax(reinterpret_cast<unsigned int*>(&C[(g*GROUP + ii)*ldc + n]),
                          __float_as_uint(v));
            }
        }
    }
}

// ---------------- launch ----------------
extern "C" void kernel_launch(void* const* d_in, const int* in_sizes, int n_in,
                              void* d_out, int out_size) {
    const float* last_pos      = (const float*)d_in[0];
    const float* last_pos_rel  = (const float*)d_in[1];
    const float* hh            = (const float*)d_in[2];
    const float* ch            = (const float*)d_in[3];
    const float* pred_traj_rel = (const float*)d_in[4];
    // d_in[5] = seq_start_end (uniform groups; unused)
    const float* W_ih = (const float*)d_in[6];
    const float* W_hh = (const float*)d_in[7];
    const float* b_ih = (const float*)d_in[8];
    const float* b_hh = (const float*)d_in[9];
    const float* Wse  = (const float*)d_in[10];
    const float* bse  = (const float*)d_in[11];
    const float* Wpos = (const float*)d_in[12];
    const float* bpos = (const float*)d_in[13];
    const float* Wp   = (const float*)d_in[14];
    const float* bp   = (const float*)d_in[15];
    const float* W1   = (const float*)d_in[16];
    const float* b1   = (const float*)d_in[17];
    const float* W2   = (const float*)d_in[18];
    const float* b2   = (const float*)d_in[19];
    const float* Wm1  = (const float*)d_in[20];
    const float* bm1  = (const float*)d_in[21];
    const float* Wm2  = (const float*)d_in[22];
    const float* bm2  = (const float*)d_in[23];

    float* out = (float*)d_out;

    float* p_h     = nullptr; cudaGetSymbolAddress((void**)&p_h,     g_h);
    float* p_acat  = nullptr; cudaGetSymbolAddress((void**)&p_acat,  g_acat);
    float* p_Wcat  = nullptr; cudaGetSymbolAddress((void**)&p_Wcat,  g_Wcat);
    float* p_bsum  = nullptr; cudaGetSymbolAddress((void**)&p_bsum,  g_bsum);
    float* p_gates = nullptr; cudaGetSymbolAddress((void**)&p_gates, g_gates);
    float* p_emb   = nullptr; cudaGetSymbolAddress((void**)&p_emb,   g_emb);
    float* p_hW1h  = nullptr; cudaGetSymbolAddress((void**)&p_hW1h,  g_hW1h);
    float* p_X1    = nullptr; cudaGetSymbolAddress((void**)&p_X1,    g_X1);
    float* p_pool  = nullptr; cudaGetSymbolAddress((void**)&p_pool,  g_pool);
    float* p_dcat  = nullptr; cudaGetSymbolAddress((void**)&p_dcat,  g_dcat);
    float* p_D1    = nullptr; cudaGetSymbolAddress((void**)&p_D1,    g_D1);

    init_kernel<<<(GATES*KCAT + 255)/256, 256>>>(hh, ch, last_pos, last_pos_rel,
                                                 W_ih, W_hh, b_ih, b_hh, Wse, bse);

    for (int t = 0; t < SEQ_LEN; t++) {
        const float* gt = pred_traj_rel + t * BATCH * 2;
        float* out_pred = out + t * BATCH * 2;

        // LSTM cell
        pack_lstm_kernel<<<(BATCH*KCAT + 255)/256, 256>>>();
        sgemm64<1><<<dim3(GATES/64, BATCH/64), 256>>>(p_acat, KCAT, p_Wcat, KCAT,
                                                      p_gates, GATES, KCAT, p_bsum, nullptr);
        lstm_elem_kernel<<<(BATCH*HD + 255)/256, 256>>>();

        // rel_pos / curr_pos / pred output / loss
        pos_loss_kernel<<<1, BATCH>>>(Wpos, bpos, gt, out_pred);

        // pool net
        emb_kernel<<<(ROWS_PN*ED + 255)/256, 256>>>(Wp, bp);
        // hW1h = h @ W1[:,64:192]^T
        sgemm64<0><<<dim3(PRE/64, BATCH/64), 256>>>(p_h, HD, W1 + ED, KCAT,
                                                    p_hW1h, PRE, HD, nullptr, nullptr);
        // X1 = relu(emb @ W1[:,0:64]^T + hW1h[row j] + b1)
        sgemm64<3><<<dim3(PRE/64, ROWS_PN/64), 256>>>(p_emb, ED, W1, KCAT,
                                                      p_X1, PRE, ED, b1, p_hW1h);
        // pool_h = max_j relu(X1 @ W2^T + b2)   (fused via atomicMax)
        zero_pool_kernel<<<(BATCH*BOTTLE + 255)/256, 256>>>();
        sgemm64<4><<<dim3(BOTTLE/64, ROWS_PN/64), 256>>>(p_X1, PRE, W2, PRE,
                                                         p_pool, BOTTLE, PRE, b2, nullptr);

        // decoder MLP: h = relu(relu([h|pool] @ Wm1^T + bm1) @ Wm2^T + bm2)
        pack_dh_kernel<<<(BATCH*DHK + 255)/256, 256>>>();
        sgemm64<2><<<dim3(MLPD/64, BATCH/64), 256>>>(p_dcat, DHK, Wm1, DHK,
                                                     p_D1, MLPD, DHK, bm1, nullptr);
        sgemm64<2><<<dim3(HD/64, BATCH/64), 256>>>(p_D1, MLPD, Wm2, MLPD,
                                                   p_h, HD, MLPD, bm2, nullptr);

        // teacher forcing: next dec_in
        decin_kernel<<<(BATCH*ED + 255)/256, 256>>>(gt, Wse, bse);
    }

    finish_kernel<<<1, 1>>>(out, out_size);
}

// round 5
// speedup vs baseline: 1.9930x; 1.9930x over previous
#include <cuda_runtime.h>
#include <cuda_bf16.h>
#include <math.h>
#include <stdint.h>

// Problem dims
#define SEQ_LEN 12
#define BATCH   512
#define NG      16
#define GROUP   32
#define HD      128      // H
#define ED      64       // E
#define PRE     512
#define BOTTLE  1024
#define MLPD    1024
#define GATES   (4*HD)   // 512
#define KCAT    (ED+HD)  // 192
#define ROWS_PN (NG*GROUP*GROUP)  // 16384
#define DHK     (HD+BOTTLE)       // 1152

// ---------------- scratch (device globals; no allocation) ----------------
__device__ float g_h[BATCH*HD];
__device__ float g_c[BATCH*HD];
__device__ float g_pos[BATCH*2];
__device__ float g_decin[BATCH*ED];
__device__ float g_acat[BATCH*KCAT];
__device__ float g_Wcat[GATES*KCAT];
__device__ float g_bsum[GATES];
__device__ float g_gates[BATCH*GATES];
__device__ float g_emb[ROWS_PN*ED];
__device__ float g_hW1h[BATCH*PRE];
__device__ __align__(16) __nv_bfloat16 g_X1hi[ROWS_PN*PRE];
__device__ __align__(16) __nv_bfloat16 g_X1lo[ROWS_PN*PRE];
__device__ __align__(16) __nv_bfloat16 g_W2hi[BOTTLE*PRE];
__device__ __align__(16) __nv_bfloat16 g_W2lo[BOTTLE*PRE];
__device__ float g_pool[BATCH*BOTTLE];
__device__ float g_dcat[BATCH*DHK];
__device__ float g_D1[BATCH*MLPD];
__device__ float g_loss;

__device__ __forceinline__ float sigmoidf(float x) { return 1.0f / (1.0f + expf(-x)); }

// ---------------- PTX helpers (base-arch only: sm_80+ features) ----------------
__device__ __forceinline__ uint32_t smem_u32(const void* p) {
    uint32_t a;
    asm("{ .reg .u64 t; cvta.to.shared.u64 t, %1; cvt.u32.u64 %0, t; }" : "=r"(a) : "l"(p));
    return a;
}
__device__ __forceinline__ void cp_async16(uint32_t s, const void* g) {
    asm volatile("cp.async.cg.shared.global [%0], [%1], 16;" :: "r"(s), "l"(g));
}
#define CP_COMMIT() asm volatile("cp.async.commit_group;" ::: "memory")
#define CP_WAIT1()  asm volatile("cp.async.wait_group 1;" ::: "memory")
#define CP_WAIT0()  asm volatile("cp.async.wait_group 0;" ::: "memory")

__device__ __forceinline__ void ldmatrix_x4(uint32_t* r, uint32_t addr) {
    asm volatile("ldmatrix.sync.aligned.m8n8.x4.shared.b16 {%0,%1,%2,%3}, [%4];"
                 : "=r"(r[0]), "=r"(r[1]), "=r"(r[2]), "=r"(r[3]) : "r"(addr));
}
__device__ __forceinline__ void mma_bf16(float* c, const uint32_t* a, uint32_t b0, uint32_t b1) {
    asm volatile("mma.sync.aligned.m16n8k16.row.col.f32.bf16.bf16.f32 "
                 "{%0,%1,%2,%3}, {%4,%5,%6,%7}, {%8,%9}, {%0,%1,%2,%3};"
                 : "+f"(c[0]), "+f"(c[1]), "+f"(c[2]), "+f"(c[3])
                 : "r"(a[0]), "r"(a[1]), "r"(a[2]), "r"(a[3]), "r"(b0), "r"(b1));
}

// ---------------- init: copy state, pack LSTM weights, dec_in0, W2 split ----------------
__global__ void init_kernel(const float* __restrict__ hh, const float* __restrict__ ch,
                            const float* __restrict__ last_pos, const float* __restrict__ last_pos_rel,
                            const float* __restrict__ Wih, const float* __restrict__ Whh,
                            const float* __restrict__ bih, const float* __restrict__ bhh,
                            const float* __restrict__ Wse, const float* __restrict__ bse,
                            const float* __restrict__ W2) {
    int idx = blockIdx.x * blockDim.x + threadIdx.x;
    if (idx < BATCH*HD) { g_h[idx] = hh[idx]; g_c[idx] = ch[idx]; }
    if (idx < BATCH*2)  g_pos[idx] = last_pos[idx];
    if (idx < BATCH*ED) {
        int b = idx / ED, e = idx % ED;
        g_decin[idx] = last_pos_rel[b*2] * Wse[e*2] + last_pos_rel[b*2+1] * Wse[e*2+1] + bse[e];
    }
    if (idx < GATES) g_bsum[idx] = bih[idx] + bhh[idx];
    if (idx < GATES*KCAT) {
        int n = idx / KCAT, k = idx % KCAT;
        g_Wcat[idx] = (k < ED) ? Wih[n*ED + k] : Whh[n*HD + (k - ED)];
    }
    if (idx < BOTTLE*PRE) {
        float w = W2[idx];
        __nv_bfloat16 hi = __float2bfloat16(w);
        g_W2hi[idx] = hi;
        g_W2lo[idx] = __float2bfloat16(w - __bfloat162float(hi));
    }
    if (idx == 0) g_loss = 0.0f;
}

// ---------------- packs ----------------
__global__ void pack_lstm_kernel() {
    int idx = blockIdx.x * blockDim.x + threadIdx.x;
    if (idx >= BATCH*KCAT) return;
    int b = idx / KCAT, k = idx % KCAT;
    g_acat[idx] = (k < ED) ? g_decin[b*ED + k] : g_h[b*HD + (k - ED)];
}

__global__ void pack_dh_kernel() {
    int idx = blockIdx.x * blockDim.x + threadIdx.x;
    if (idx >= BATCH*DHK) return;
    int b = idx / DHK, k = idx % DHK;
    g_dcat[idx] = (k < HD) ? g_h[b*HD + k] : g_pool[b*BOTTLE + (k - HD)];
}

// ---------------- LSTM elementwise ----------------
__global__ void lstm_elem_kernel() {
    int idx = blockIdx.x * blockDim.x + threadIdx.x;
    if (idx >= BATCH*HD) return;
    int b = idx / HD, j = idx % HD;
    const float* gr = g_gates + b*GATES;
    float ig = gr[j], fg = gr[HD + j], gg = gr[2*HD + j], og = gr[3*HD + j];
    float c = sigmoidf(fg) * g_c[idx] + sigmoidf(ig) * tanhf(gg);
    g_c[idx] = c;
    g_h[idx] = sigmoidf(og) * tanhf(c);
}

// ---------------- rel_pos, curr_pos, pred output, loss ----------------
__global__ void pos_loss_kernel(const float* __restrict__ Wpos, const float* __restrict__ bpos,
                                const float* __restrict__ gt, float* __restrict__ out_pred) {
    int b = threadIdx.x;
    const float* hr = g_h + b*HD;
    float ax = 0.f, ay = 0.f;
    #pragma unroll 8
    for (int k = 0; k < HD; k++) { float hv = hr[k]; ax += hv * Wpos[k]; ay += hv * Wpos[HD + k]; }
    float rx = ax + bpos[0], ry = ay + bpos[1];
    out_pred[b*2]   = rx;
    out_pred[b*2+1] = ry;
    g_pos[b*2]   += rx;
    g_pos[b*2+1] += ry;
    float dx = rx - gt[b*2], dy = ry - gt[b*2+1];
    __shared__ float sd[BATCH];
    sd[b] = dx*dx + dy*dy;
    __syncthreads();
    for (int s = BATCH/2; s > 0; s >>= 1) {
        if (b < s) sd[b] += sd[b + s];
        __syncthreads();
    }
    if (b == 0) g_loss += sd[0] / (float)(BATCH*2);
}

// ---------------- pairwise rel-pos embedding ----------------
__global__ void emb_kernel(const float* __restrict__ Wp, const float* __restrict__ bp) {
    int idx = blockIdx.x * blockDim.x + threadIdx.x;
    if (idx >= ROWS_PN*ED) return;
    int r = idx >> 6, e = idx & 63;
    int g = r >> 10, i = (r >> 5) & 31, j = r & 31;
    int bi = g*GROUP + i, bj = g*GROUP + j;
    float rx = g_pos[bj*2]   - g_pos[bi*2];
    float ry = g_pos[bj*2+1] - g_pos[bi*2+1];
    g_emb[idx] = rx * Wp[e*2] + ry * Wp[e*2+1] + bp[e];
}

// ---------------- next dec_in ----------------
__global__ void decin_kernel(const float* __restrict__ gt,
                             const float* __restrict__ Wse, const float* __restrict__ bse) {
    int idx = blockIdx.x * blockDim.x + threadIdx.x;
    if (idx >= BATCH*ED) return;
    int b = idx / ED, e = idx % ED;
    g_decin[idx] = gt[b*2] * Wse[e*2] + gt[b*2+1] * Wse[e*2+1] + bse[e];
}

__global__ void finish_kernel(float* __restrict__ out, int out_size) {
    if (out_size > SEQ_LEN*BATCH*2) out[SEQ_LEN*BATCH*2] = g_loss;
}

// ---------------- SIMT SGEMM: C = A(MxK) * W(NxK)^T ----------------
// MODE 0: C = acc; MODE 1: +bias; MODE 2: relu(+bias)
// MODE 3: X1: v=relu(acc+bias+aux[(g*32+j)*PRE+n]); write bf16 hi/lo to g_X1hi/g_X1lo
template<int MODE>
__global__ void sgemm64(const float* __restrict__ A, int lda,
                        const float* __restrict__ W, int ldw,
                        float* __restrict__ C, int ldc, int K,
                        const float* __restrict__ bias,
                        const float* __restrict__ aux) {
    __shared__ float As[64][17];
    __shared__ float Ws[64][17];
    int tid = threadIdx.x;
    int m0 = blockIdx.y * 64, n0 = blockIdx.x * 64;
    int ty = tid >> 4, tx = tid & 15;
    float acc[4][4] = {};

    for (int k0 = 0; k0 < K; k0 += 16) {
        #pragma unroll
        for (int l = tid; l < 64*16; l += 256) {
            int r = l >> 4, c = l & 15;
            As[r][c] = A[(m0 + r) * lda + k0 + c];
            Ws[r][c] = W[(n0 + r) * ldw + k0 + c];
        }
        __syncthreads();
        #pragma unroll
        for (int kk = 0; kk < 16; kk++) {
            float a[4], w[4];
            #pragma unroll
            for (int i = 0; i < 4; i++) { a[i] = As[ty*4 + i][kk]; w[i] = Ws[tx*4 + i][kk]; }
            #pragma unroll
            for (int i = 0; i < 4; i++)
                #pragma unroll
                for (int j = 0; j < 4; j++) acc[i][j] += a[i] * w[j];
        }
        __syncthreads();
    }

    #pragma unroll
    for (int i = 0; i < 4; i++) {
        int m = m0 + ty*4 + i;
        #pragma unroll
        for (int j = 0; j < 4; j++) {
            int n = n0 + tx*4 + j;
            float v = acc[i][j];
            if (MODE == 0) {
                C[m*ldc + n] = v;
            } else if (MODE == 1) {
                C[m*ldc + n] = v + bias[n];
            } else if (MODE == 2) {
                C[m*ldc + n] = fmaxf(v + bias[n], 0.0f);
            } else { // MODE 3
                int g = m >> 10, jj = m & 31;
                v = fmaxf(v + bias[n] + aux[(g*GROUP + jj)*PRE + n], 0.0f);
                __nv_bfloat16 hi = __float2bfloat16(v);
                g_X1hi[m*PRE + n] = hi;
                g_X1lo[m*PRE + n] = __float2bfloat16(v - __bfloat162float(hi));
            }
        }
    }
}

// ---------------- HMMA GEMM2: pool = relu(max_j(X1 @ W2^T) + b2) ----------------
// M=16384, N=1024, K=512, bf16 3-term split via mma.sync.m16n8k16.
// CTA tile 128x128, 8 warps (2x4), warp tile 64x32, K-chunk 64, cp.async 2-stage.
#define G2_LDA      72                           // padded smem row stride (bf16 elems)
#define G2_ABYTES   (128 * G2_LDA * 2)           // 18432 per matrix
#define G2_STAGE    (2 * G2_ABYTES)              // A + B
#define G2_DYN      (2 * G2_STAGE)               // 73728 (also covers 128x132 f32 C tile)
#define G2_NCHUNK   24                           // 3 terms x (512/64)

__global__ void __launch_bounds__(256, 1)
gemm2_kernel(const float* __restrict__ b2, float* __restrict__ pool) {
    extern __shared__ char dyn[];
    const int tid  = threadIdx.x;
    const int lane = tid & 31;
    const int wid  = tid >> 5;
    const int wm   = wid >> 2;      // 0..1
    const int wn   = wid & 3;       // 0..3
    const int n0 = blockIdx.x * 128;
    const int m0 = blockIdx.y * 128;

    uint32_t sbase = smem_u32(dyn);

    const __nv_bfloat16* Aterm[3] = { g_X1hi, g_X1lo, g_X1hi };
    const __nv_bfloat16* Bterm[3] = { g_W2hi, g_W2hi, g_W2lo };

    float acc[4][4][4] = {};

    // ldmatrix address components (fixed per thread)
    const int a_row  = wm * 64 + (lane & 15);
    const int a_colg = (lane >> 4) * 8;
    const int b_row  = wn * 32 + ((lane >> 4) & 1) * 8 + (lane & 7);
    const int b_colg = ((lane >> 3) & 1) * 8;

    // load chunk c into stage s: each matrix is 128 rows x 64 bf16 cols
    // = 128 rows x 8 segments of 16B = 1024 transfers per matrix.
    auto load_chunk = [&](int c, int s) {
        int term = c >> 3, kc = (c & 7) * 64;
        const __nv_bfloat16* Ap = Aterm[term] + (size_t)m0 * PRE + kc;
        const __nv_bfloat16* Bp = Bterm[term] + (size_t)n0 * PRE + kc;
        uint32_t sA = sbase + s * G2_STAGE;
        uint32_t sB = sA + G2_ABYTES;
        #pragma unroll
        for (int u = 0; u < 4; u++) {
            int idx = tid + u * 256;          // 0..1023
            int row = idx >> 3, seg = idx & 7;
            uint32_t off = (uint32_t)(row * G2_LDA + seg * 8) * 2;
            cp_async16(sA + off, Ap + (size_t)row * PRE + seg * 8);
            cp_async16(sB + off, Bp + (size_t)row * PRE + seg * 8);
        }
    };

    load_chunk(0, 0);
    CP_COMMIT();

    for (int c = 0; c < G2_NCHUNK; c++) {
        if (c + 1 < G2_NCHUNK) {
            load_chunk(c + 1, (c + 1) & 1);
            CP_COMMIT();
            CP_WAIT1();
        } else {
            CP_WAIT0();
        }
        __syncthreads();

        uint32_t sA = sbase + (c & 1) * G2_STAGE;
        uint32_t sB = sA + G2_ABYTES;
        #pragma unroll
        for (int ks = 0; ks < 4; ks++) {
            uint32_t afr[4][4];
            #pragma unroll
            for (int mf = 0; mf < 4; mf++)
                ldmatrix_x4(afr[mf], sA + (uint32_t)((a_row + mf*16) * G2_LDA + ks*16 + a_colg) * 2);
            uint32_t bfr[2][4];
            #pragma unroll
            for (int nf2 = 0; nf2 < 2; nf2++)
                ldmatrix_x4(bfr[nf2], sB + (uint32_t)((b_row + nf2*16) * G2_LDA + ks*16 + b_colg) * 2);
            #pragma unroll
            for (int mf = 0; mf < 4; mf++)
                #pragma unroll
                for (int nf = 0; nf < 4; nf++)
                    mma_bf16(acc[mf][nf], afr[mf], bfr[nf>>1][(nf&1)*2], bfr[nf>>1][(nf&1)*2 + 1]);
        }
        __syncthreads();
    }

    // Epilogue: dump fp32 tile to smem, reduce max over 32-row neighbor groups.
    float* Cs = (float*)dyn;    // 128 x 132
    #pragma unroll
    for (int mf = 0; mf < 4; mf++) {
        int r = wm * 64 + mf * 16 + (lane >> 2);
        #pragma unroll
        for (int nf = 0; nf < 4; nf++) {
            int cc = wn * 32 + nf * 8 + (lane & 3) * 2;
            Cs[r * 132 + cc]           = acc[mf][nf][0];
            Cs[r * 132 + cc + 1]       = acc[mf][nf][1];
            Cs[(r + 8) * 132 + cc]     = acc[mf][nf][2];
            Cs[(r + 8) * 132 + cc + 1] = acc[mf][nf][3];
        }
    }
    __syncthreads();

    #pragma unroll
    for (int u = 0; u < 2; u++) {
        int o = tid + u * 256;          // 0..511
        int grp = o >> 7, col = o & 127;
        float v = -3.0e38f;
        #pragma unroll 8
        for (int r = 0; r < 32; r++)
            v = fmaxf(v, Cs[(grp * 32 + r) * 132 + col]);
        int n = n0 + col;
        pool[(blockIdx.y * 4 + grp) * BOTTLE + n] = fmaxf(v + b2[n], 0.0f);
    }
}

// ---------------- launch ----------------
extern "C" void kernel_launch(void* const* d_in, const int* in_sizes, int n_in,
                              void* d_out, int out_size) {
    const float* last_pos      = (const float*)d_in[0];
    const float* last_pos_rel  = (const float*)d_in[1];
    const float* hh            = (const float*)d_in[2];
    const float* ch            = (const float*)d_in[3];
    const float* pred_traj_rel = (const float*)d_in[4];
    const float* W_ih = (const float*)d_in[6];
    const float* W_hh = (const float*)d_in[7];
    const float* b_ih = (const float*)d_in[8];
    const float* b_hh = (const float*)d_in[9];
    const float* Wse  = (const float*)d_in[10];
    const float* bse  = (const float*)d_in[11];
    const float* Wpos = (const float*)d_in[12];
    const float* bpos = (const float*)d_in[13];
    const float* Wp   = (const float*)d_in[14];
    const float* bp   = (const float*)d_in[15];
    const float* W1   = (const float*)d_in[16];
    const float* b1   = (const float*)d_in[17];
    const float* W2   = (const float*)d_in[18];
    const float* b2   = (const float*)d_in[19];
    const float* Wm1  = (const float*)d_in[20];
    const float* bm1  = (const float*)d_in[21];
    const float* Wm2  = (const float*)d_in[22];
    const float* bm2  = (const float*)d_in[23];

    float* out = (float*)d_out;

    float* p_h     = nullptr; cudaGetSymbolAddress((void**)&p_h,     g_h);
    float* p_acat  = nullptr; cudaGetSymbolAddress((void**)&p_acat,  g_acat);
    float* p_Wcat  = nullptr; cudaGetSymbolAddress((void**)&p_Wcat,  g_Wcat);
    float* p_bsum  = nullptr; cudaGetSymbolAddress((void**)&p_bsum,  g_bsum);
    float* p_gates = nullptr; cudaGetSymbolAddress((void**)&p_gates, g_gates);
    float* p_emb   = nullptr; cudaGetSymbolAddress((void**)&p_emb,   g_emb);
    float* p_hW1h  = nullptr; cudaGetSymbolAddress((void**)&p_hW1h,  g_hW1h);
    float* p_pool  = nullptr; cudaGetSymbolAddress((void**)&p_pool,  g_pool);
    float* p_dcat  = nullptr; cudaGetSymbolAddress((void**)&p_dcat,  g_dcat);
    float* p_D1    = nullptr; cudaGetSymbolAddress((void**)&p_D1,    g_D1);

    cudaFuncSetAttribute(gemm2_kernel, cudaFuncAttributeMaxDynamicSharedMemorySize, G2_DYN);

    init_kernel<<<(BOTTLE*PRE + 255)/256, 256>>>(hh, ch, last_pos, last_pos_rel,
                                                 W_ih, W_hh, b_ih, b_hh, Wse, bse, W2);

    for (int t = 0; t < SEQ_LEN; t++) {
        const float* gt = pred_traj_rel + t * BATCH * 2;
        float* out_pred = out + t * BATCH * 2;

        // LSTM cell
        pack_lstm_kernel<<<(BATCH*KCAT + 255)/256, 256>>>();
        sgemm64<1><<<dim3(GATES/64, BATCH/64), 256>>>(p_acat, KCAT, p_Wcat, KCAT,
                                                      p_gates, GATES, KCAT, p_bsum, nullptr);
        lstm_elem_kernel<<<(BATCH*HD + 255)/256, 256>>>();

        // rel_pos / curr_pos / pred output / loss
        pos_loss_kernel<<<1, BATCH>>>(Wpos, bpos, gt, out_pred);

        // pool net
        emb_kernel<<<(ROWS_PN*ED + 255)/256, 256>>>(Wp, bp);
        sgemm64<0><<<dim3(PRE/64, BATCH/64), 256>>>(p_h, HD, W1 + ED, KCAT,
                                                    p_hW1h, PRE, HD, nullptr, nullptr);
        // X1 = relu(emb @ W1e^T + hW1h[j] + b1) -> bf16 hi/lo
        sgemm64<3><<<dim3(PRE/64, ROWS_PN/64), 256>>>(p_emb, ED, W1, KCAT,
                                                      nullptr, PRE, ED, b1, p_hW1h);
        // pool = relu(max_j(X1 @ W2^T) + b2) via HMMA split-bf16
        gemm2_kernel<<<dim3(BOTTLE/128, ROWS_PN/128), 256, G2_DYN>>>(b2, p_pool);

        // decoder MLP
        pack_dh_kernel<<<(BATCH*DHK + 255)/256, 256>>>();
        sgemm64<2><<<dim3(MLPD/64, BATCH/64), 256>>>(p_dcat, DHK, Wm1, DHK,
                                                     p_D1, MLPD, DHK, bm1, nullptr);
        sgemm64<2><<<dim3(HD/64, BATCH/64), 256>>>(p_D1, MLPD, Wm2, MLPD,
                                                   p_h, HD, MLPD, bm2, nullptr);

        decin_kernel<<<(BATCH*ED + 255)/256, 256>>>(gt, Wse, bse);
    }

    finish_kernel<<<1, 1>>>(out, out_size);
}

// round 6
// speedup vs baseline: 2.0799x; 1.0436x over previous
#include <cuda_runtime.h>
#include <cuda_bf16.h>
#include <math.h>
#include <stdint.h>

// Problem dims
#define SEQ_LEN 12
#define BATCH   512
#define NG      16
#define GROUP   32
#define HD      128      // H
#define ED      64       // E
#define PRE     512
#define BOTTLE  1024
#define MLPD    1024
#define GATES   (4*HD)   // 512
#define KCAT    (ED+HD)  // 192
#define ROWS_PN (NG*GROUP*GROUP)  // 16384
#define DHK     (HD+BOTTLE)       // 1152

// ---------------- scratch (device globals; no allocation) ----------------
__device__ float g_h[BATCH*HD];
__device__ float g_c[BATCH*HD];
__device__ float g_pos[BATCH*2];
__device__ float g_decin[BATCH*ED];
__device__ float g_acat[BATCH*KCAT];
__device__ float g_Wcat[GATES*KCAT];
__device__ float g_bsum[GATES];
__device__ float g_gates[BATCH*GATES];
__device__ __align__(16) __nv_bfloat16 g_embhi[ROWS_PN*ED];
__device__ __align__(16) __nv_bfloat16 g_emblo[ROWS_PN*ED];
__device__ __align__(16) __nv_bfloat16 g_W1ehi[PRE*ED];
__device__ __align__(16) __nv_bfloat16 g_W1elo[PRE*ED];
__device__ float g_hW1h[BATCH*PRE];
__device__ __align__(16) __nv_bfloat16 g_X1hi[ROWS_PN*PRE];
__device__ __align__(16) __nv_bfloat16 g_X1lo[ROWS_PN*PRE];
__device__ __align__(16) __nv_bfloat16 g_W2hi[BOTTLE*PRE];
__device__ __align__(16) __nv_bfloat16 g_W2lo[BOTTLE*PRE];
__device__ float g_pool[BATCH*BOTTLE];
__device__ float g_dcat[BATCH*DHK];
__device__ float g_D1[BATCH*MLPD];
__device__ float g_loss;

__device__ __forceinline__ float sigmoidf(float x) { return 1.0f / (1.0f + expf(-x)); }

// ---------------- PTX helpers (base-arch only: sm_80+ features) ----------------
__device__ __forceinline__ uint32_t smem_u32(const void* p) {
    uint32_t a;
    asm("{ .reg .u64 t; cvta.to.shared.u64 t, %1; cvt.u32.u64 %0, t; }" : "=r"(a) : "l"(p));
    return a;
}
__device__ __forceinline__ void cp_async16(uint32_t s, const void* g) {
    asm volatile("cp.async.cg.shared.global [%0], [%1], 16;" :: "r"(s), "l"(g));
}
#define CP_COMMIT() asm volatile("cp.async.commit_group;" ::: "memory")
#define CP_WAIT1()  asm volatile("cp.async.wait_group 1;" ::: "memory")
#define CP_WAIT0()  asm volatile("cp.async.wait_group 0;" ::: "memory")

__device__ __forceinline__ void ldmatrix_x4(uint32_t* r, uint32_t addr) {
    asm volatile("ldmatrix.sync.aligned.m8n8.x4.shared.b16 {%0,%1,%2,%3}, [%4];"
                 : "=r"(r[0]), "=r"(r[1]), "=r"(r[2]), "=r"(r[3]) : "r"(addr));
}
__device__ __forceinline__ void mma_bf16(float* c, const uint32_t* a, uint32_t b0, uint32_t b1) {
    asm volatile("mma.sync.aligned.m16n8k16.row.col.f32.bf16.bf16.f32 "
                 "{%0,%1,%2,%3}, {%4,%5,%6,%7}, {%8,%9}, {%0,%1,%2,%3};"
                 : "+f"(c[0]), "+f"(c[1]), "+f"(c[2]), "+f"(c[3])
                 : "r"(a[0]), "r"(a[1]), "r"(a[2]), "r"(a[3]), "r"(b0), "r"(b1));
}

// ---------------- init ----------------
__global__ void init_kernel(const float* __restrict__ hh, const float* __restrict__ ch,
                            const float* __restrict__ last_pos, const float* __restrict__ last_pos_rel,
                            const float* __restrict__ Wih, const float* __restrict__ Whh,
                            const float* __restrict__ bih, const float* __restrict__ bhh,
                            const float* __restrict__ Wse, const float* __restrict__ bse,
                            const float* __restrict__ W1, const float* __restrict__ W2) {
    int idx = blockIdx.x * blockDim.x + threadIdx.x;
    if (idx < BATCH*HD) { g_h[idx] = hh[idx]; g_c[idx] = ch[idx]; }
    if (idx < BATCH*2)  g_pos[idx] = last_pos[idx];
    if (idx < BATCH*ED) {
        int b = idx / ED, e = idx % ED;
        g_decin[idx] = last_pos_rel[b*2] * Wse[e*2] + last_pos_rel[b*2+1] * Wse[e*2+1] + bse[e];
    }
    if (idx < GATES) g_bsum[idx] = bih[idx] + bhh[idx];
    if (idx < GATES*KCAT) {
        int n = idx / KCAT, k = idx % KCAT;
        g_Wcat[idx] = (k < ED) ? Wih[n*ED + k] : Whh[n*HD + (k - ED)];
    }
    if (idx < PRE*ED) {
        int n = idx >> 6, k = idx & 63;
        float w = W1[n*KCAT + k];
        __nv_bfloat16 hi = __float2bfloat16(w);
        g_W1ehi[idx] = hi;
        g_W1elo[idx] = __float2bfloat16(w - __bfloat162float(hi));
    }
    if (idx < BOTTLE*PRE) {
        float w = W2[idx];
        __nv_bfloat16 hi = __float2bfloat16(w);
        g_W2hi[idx] = hi;
        g_W2lo[idx] = __float2bfloat16(w - __bfloat162float(hi));
    }
    if (idx == 0) g_loss = 0.0f;
}

// ---------------- packs ----------------
__global__ void pack_lstm_kernel() {
    int idx = blockIdx.x * blockDim.x + threadIdx.x;
    if (idx >= BATCH*KCAT) return;
    int b = idx / KCAT, k = idx % KCAT;
    g_acat[idx] = (k < ED) ? g_decin[b*ED + k] : g_h[b*HD + (k - ED)];
}

__global__ void pack_dh_kernel() {
    int idx = blockIdx.x * blockDim.x + threadIdx.x;
    if (idx >= BATCH*DHK) return;
    int b = idx / DHK, k = idx % DHK;
    g_dcat[idx] = (k < HD) ? g_h[b*HD + k] : g_pool[b*BOTTLE + (k - HD)];
}

// ---------------- LSTM elementwise ----------------
__global__ void lstm_elem_kernel() {
    int idx = blockIdx.x * blockDim.x + threadIdx.x;
    if (idx >= BATCH*HD) return;
    int b = idx / HD, j = idx % HD;
    const float* gr = g_gates + b*GATES;
    float ig = gr[j], fg = gr[HD + j], gg = gr[2*HD + j], og = gr[3*HD + j];
    float c = sigmoidf(fg) * g_c[idx] + sigmoidf(ig) * tanhf(gg);
    g_c[idx] = c;
    g_h[idx] = sigmoidf(og) * tanhf(c);
}

// ---------------- rel_pos, curr_pos, pred output, loss ----------------
__global__ void pos_loss_kernel(const float* __restrict__ Wpos, const float* __restrict__ bpos,
                                const float* __restrict__ gt, float* __restrict__ out_pred) {
    int b = threadIdx.x;
    const float* hr = g_h + b*HD;
    float ax = 0.f, ay = 0.f;
    #pragma unroll 8
    for (int k = 0; k < HD; k++) { float hv = hr[k]; ax += hv * Wpos[k]; ay += hv * Wpos[HD + k]; }
    float rx = ax + bpos[0], ry = ay + bpos[1];
    out_pred[b*2]   = rx;
    out_pred[b*2+1] = ry;
    g_pos[b*2]   += rx;
    g_pos[b*2+1] += ry;
    float dx = rx - gt[b*2], dy = ry - gt[b*2+1];
    __shared__ float sd[BATCH];
    sd[b] = dx*dx + dy*dy;
    __syncthreads();
    for (int s = BATCH/2; s > 0; s >>= 1) {
        if (b < s) sd[b] += sd[b + s];
        __syncthreads();
    }
    if (b == 0) g_loss += sd[0] / (float)(BATCH*2);
}

// ---------------- pairwise rel-pos embedding -> bf16 hi/lo ----------------
__global__ void emb_kernel(const float* __restrict__ Wp, const float* __restrict__ bp) {
    int idx = blockIdx.x * blockDim.x + threadIdx.x;
    if (idx >= ROWS_PN*ED) return;
    int r = idx >> 6, e = idx & 63;
    int g = r >> 10, i = (r >> 5) & 31, j = r & 31;
    int bi = g*GROUP + i, bj = g*GROUP + j;
    float rx = g_pos[bj*2]   - g_pos[bi*2];
    float ry = g_pos[bj*2+1] - g_pos[bi*2+1];
    float v = rx * Wp[e*2] + ry * Wp[e*2+1] + bp[e];
    __nv_bfloat16 hi = __float2bfloat16(v);
    g_embhi[idx] = hi;
    g_emblo[idx] = __float2bfloat16(v - __bfloat162float(hi));
}

// ---------------- next dec_in ----------------
__global__ void decin_kernel(const float* __restrict__ gt,
                             const float* __restrict__ Wse, const float* __restrict__ bse) {
    int idx = blockIdx.x * blockDim.x + threadIdx.x;
    if (idx >= BATCH*ED) return;
    int b = idx / ED, e = idx % ED;
    g_decin[idx] = gt[b*2] * Wse[e*2] + gt[b*2+1] * Wse[e*2+1] + bse[e];
}

__global__ void finish_kernel(float* __restrict__ out, int out_size) {
    if (out_size > SEQ_LEN*BATCH*2) out[SEQ_LEN*BATCH*2] = g_loss;
}

// ---------------- SIMT SGEMM: C = A(MxK) * W(NxK)^T ----------------
// MODE 0: C = acc; MODE 1: +bias; MODE 2: relu(+bias)
template<int MODE>
__global__ void sgemm64(const float* __restrict__ A, int lda,
                        const float* __restrict__ W, int ldw,
                        float* __restrict__ C, int ldc, int K,
                        const float* __restrict__ bias) {
    __shared__ float As[64][17];
    __shared__ float Ws[64][17];
    int tid = threadIdx.x;
    int m0 = blockIdx.y * 64, n0 = blockIdx.x * 64;
    int ty = tid >> 4, tx = tid & 15;
    float acc[4][4] = {};

    for (int k0 = 0; k0 < K; k0 += 16) {
        #pragma unroll
        for (int l = tid; l < 64*16; l += 256) {
            int r = l >> 4, c = l & 15;
            As[r][c] = A[(m0 + r) * lda + k0 + c];
            Ws[r][c] = W[(n0 + r) * ldw + k0 + c];
        }
        __syncthreads();
        #pragma unroll
        for (int kk = 0; kk < 16; kk++) {
            float a[4], w[4];
            #pragma unroll
            for (int i = 0; i < 4; i++) { a[i] = As[ty*4 + i][kk]; w[i] = Ws[tx*4 + i][kk]; }
            #pragma unroll
            for (int i = 0; i < 4; i++)
                #pragma unroll
                for (int j = 0; j < 4; j++) acc[i][j] += a[i] * w[j];
        }
        __syncthreads();
    }

    #pragma unroll
    for (int i = 0; i < 4; i++) {
        int m = m0 + ty*4 + i;
        #pragma unroll
        for (int j = 0; j < 4; j++) {
            int n = n0 + tx*4 + j;
            float v = acc[i][j];
            if (MODE == 0) C[m*ldc + n] = v;
            else if (MODE == 1) C[m*ldc + n] = v + bias[n];
            else C[m*ldc + n] = fmaxf(v + bias[n], 0.0f);
        }
    }
}

// ---------------- HMMA GEMM (256x128 CTA, 8 warps 4x2, warp tile 64x64) ----------------
// C = sum over 3 terms of Aterm(Mx K64chunks) * Bterm^T, K-chunk 64, 2-stage cp.async.
// EPI 0: pool epilogue — max over 32-row groups, +b2, relu, write g_pool rows.
// EPI 1: X1 epilogue — +b1 + hW1h[(m>>10)*32+(m&31)], relu, write bf16 hi/lo packed.
#define HG_LDA     72
#define HG_ASTAGE  (256 * HG_LDA * 2)    // 36864
#define HG_BSTAGE  (128 * HG_LDA * 2)    // 18432
#define HG_STAGE   (HG_ASTAGE + HG_BSTAGE)
#define HG_DYN     (2 * HG_STAGE)        // 110592

template<int EPI>
__global__ void __launch_bounds__(256, 1)
hgemm(const __nv_bfloat16* __restrict__ Ahi, const __nv_bfloat16* __restrict__ Alo,
      const __nv_bfloat16* __restrict__ Bhi, const __nv_bfloat16* __restrict__ Blo,
      int lda, int ldb, int nchunkper,
      const float* __restrict__ bias, const float* __restrict__ aux,
      float* __restrict__ outp) {
    extern __shared__ char dyn[];
    const int tid  = threadIdx.x;
    const int lane = tid & 31;
    const int wid  = tid >> 5;
    const int wm   = wid >> 1;      // 0..3
    const int wn   = wid & 1;       // 0..1
    const int n0 = blockIdx.x * 128;
    const int m0 = blockIdx.y * 256;
    const int NC = 3 * nchunkper;

    uint32_t sbase = smem_u32(dyn);

    float acc[4][8][4] = {};

    const int a_row  = wm * 64 + (lane & 15);
    const int a_colg = (lane >> 4) * 8;
    const int b_sub  = ((lane >> 4) & 1) * 8 + (lane & 7);
    const int b_colg = ((lane >> 3) & 1) * 8;

    auto load_chunk = [&](int c, int s) {
        int term = c / nchunkper, kc = (c % nchunkper) * 64;
        const __nv_bfloat16* Ap = (term == 1 ? Alo : Ahi) + (size_t)m0 * lda + kc;
        const __nv_bfloat16* Bp = (term == 2 ? Blo : Bhi) + (size_t)n0 * ldb + kc;
        uint32_t sA = sbase + s * HG_STAGE;
        uint32_t sB = sA + HG_ASTAGE;
        #pragma unroll
        for (int u = 0; u < 8; u++) {
            int idx = tid + u * 256;          // 0..2047
            int row = idx >> 3, seg = idx & 7;
            cp_async16(sA + (uint32_t)(row * HG_LDA + seg * 8) * 2,
                       Ap + (size_t)row * lda + seg * 8);
        }
        #pragma unroll
        for (int u = 0; u < 4; u++) {
            int idx = tid + u * 256;          // 0..1023
            int row = idx >> 3, seg = idx & 7;
            cp_async16(sB + (uint32_t)(row * HG_LDA + seg * 8) * 2,
                       Bp + (size_t)row * ldb + seg * 8);
        }
    };

    load_chunk(0, 0);
    CP_COMMIT();

    for (int c = 0; c < NC; c++) {
        if (c + 1 < NC) {
            load_chunk(c + 1, (c + 1) & 1);
            CP_COMMIT();
            CP_WAIT1();
        } else {
            CP_WAIT0();
        }
        __syncthreads();

        uint32_t sA = sbase + (c & 1) * HG_STAGE;
        uint32_t sB = sA + HG_ASTAGE;
        #pragma unroll
        for (int ks = 0; ks < 4; ks++) {
            uint32_t afr[4][4];
            #pragma unroll
            for (int mf = 0; mf < 4; mf++)
                ldmatrix_x4(afr[mf], sA + (uint32_t)((a_row + mf*16) * HG_LDA + ks*16 + a_colg) * 2);
            uint32_t bfr[4][4];
            #pragma unroll
            for (int nf2 = 0; nf2 < 4; nf2++)
                ldmatrix_x4(bfr[nf2], sB + (uint32_t)((wn*64 + nf2*16 + b_sub) * HG_LDA + ks*16 + b_colg) * 2);
            #pragma unroll
            for (int mf = 0; mf < 4; mf++)
                #pragma unroll
                for (int nf = 0; nf < 8; nf++)
                    mma_bf16(acc[mf][nf], afr[mf], bfr[nf>>1][(nf&1)*2], bfr[nf>>1][(nf&1)*2 + 1]);
        }
        __syncthreads();
    }

    if (EPI == 0) {
        // pool: warp owns rows m0+wm*64 .. +63 = two full 32-row groups.
        #pragma unroll
        for (int half = 0; half < 2; half++) {
            int pr = blockIdx.y * 8 + wm * 2 + half;    // pool row = m/32
            #pragma unroll
            for (int nf = 0; nf < 8; nf++) {
                float v0 = fmaxf(fmaxf(acc[2*half][nf][0], acc[2*half][nf][2]),
                                 fmaxf(acc[2*half+1][nf][0], acc[2*half+1][nf][2]));
                float v1 = fmaxf(fmaxf(acc[2*half][nf][1], acc[2*half][nf][3]),
                                 fmaxf(acc[2*half+1][nf][1], acc[2*half+1][nf][3]));
                #pragma unroll
                for (int d = 4; d < 32; d <<= 1) {
                    v0 = fmaxf(v0, __shfl_xor_sync(0xffffffffu, v0, d));
                    v1 = fmaxf(v1, __shfl_xor_sync(0xffffffffu, v1, d));
                }
                if ((lane >> 2) == 0) {
                    int n = n0 + wn*64 + nf*8 + (lane & 3)*2;
                    outp[pr * BOTTLE + n]     = fmaxf(v0 + bias[n], 0.0f);
                    outp[pr * BOTTLE + n + 1] = fmaxf(v1 + bias[n + 1], 0.0f);
                }
            }
        }
    } else {
        // X1: +bias + aux[(m>>10)*32 + (m&31)], relu, write bf16 hi/lo packed pairs.
        #pragma unroll
        for (int mf = 0; mf < 4; mf++) {
            int R  = m0 + wm*64 + mf*16 + (lane >> 2);
            int R8 = R + 8;
            const float* aux0 = aux + (size_t)((R  >> 10)*32 + (R  & 31)) * PRE;
            const float* aux8 = aux + (size_t)((R8 >> 10)*32 + (R8 & 31)) * PRE;
            #pragma unroll
            for (int nf = 0; nf < 8; nf++) {
                int n = n0 + wn*64 + nf*8 + (lane & 3)*2;
                float b0 = bias[n], b1v = bias[n + 1];
                float v0 = fmaxf(acc[mf][nf][0] + b0  + aux0[n],     0.0f);
                float v1 = fmaxf(acc[mf][nf][1] + b1v + aux0[n + 1], 0.0f);
                float v2 = fmaxf(acc[mf][nf][2] + b0  + aux8[n],     0.0f);
                float v3 = fmaxf(acc[mf][nf][3] + b1v + aux8[n + 1], 0.0f);
                __nv_bfloat162 h01, h23, l01, l23;
                h01.x = __float2bfloat16(v0); h01.y = __float2bfloat16(v1);
                h23.x = __float2bfloat16(v2); h23.y = __float2bfloat16(v3);
                l01.x = __float2bfloat16(v0 - __bfloat162float(h01.x));
                l01.y = __float2bfloat16(v1 - __bfloat162float(h01.y));
                l23.x = __float2bfloat16(v2 - __bfloat162float(h23.x));
                l23.y = __float2bfloat16(v3 - __bfloat162float(h23.y));
                *reinterpret_cast<__nv_bfloat162*>(&g_X1hi[(size_t)R  * PRE + n]) = h01;
                *reinterpret_cast<__nv_bfloat162*>(&g_X1hi[(size_t)R8 * PRE + n]) = h23;
                *reinterpret_cast<__nv_bfloat162*>(&g_X1lo[(size_t)R  * PRE + n]) = l01;
                *reinterpret_cast<__nv_bfloat162*>(&g_X1lo[(size_t)R8 * PRE + n]) = l23;
            }
        }
    }
}

// ---------------- launch ----------------
extern "C" void kernel_launch(void* const* d_in, const int* in_sizes, int n_in,
                              void* d_out, int out_size) {
    const float* last_pos      = (const float*)d_in[0];
    const float* last_pos_rel  = (const float*)d_in[1];
    const float* hh            = (const float*)d_in[2];
    const float* ch            = (const float*)d_in[3];
    const float* pred_traj_rel = (const float*)d_in[4];
    const float* W_ih = (const float*)d_in[6];
    const float* W_hh = (const float*)d_in[7];
    const float* b_ih = (const float*)d_in[8];
    const float* b_hh = (const float*)d_in[9];
    const float* Wse  = (const float*)d_in[10];
    const float* bse  = (const float*)d_in[11];
    const float* Wpos = (const float*)d_in[12];
    const float* bpos = (const float*)d_in[13];
    const float* Wp   = (const float*)d_in[14];
    const float* bp   = (const float*)d_in[15];
    const float* W1   = (const float*)d_in[16];
    const float* b1   = (const float*)d_in[17];
    const float* W2   = (const float*)d_in[18];
    const float* b2   = (const float*)d_in[19];
    const float* Wm1  = (const float*)d_in[20];
    const float* bm1  = (const float*)d_in[21];
    const float* Wm2  = (const float*)d_in[22];
    const float* bm2  = (const float*)d_in[23];

    float* out = (float*)d_out;

    float* p_h     = nullptr; cudaGetSymbolAddress((void**)&p_h,     g_h);
    float* p_acat  = nullptr; cudaGetSymbolAddress((void**)&p_acat,  g_acat);
    float* p_Wcat  = nullptr; cudaGetSymbolAddress((void**)&p_Wcat,  g_Wcat);
    float* p_bsum  = nullptr; cudaGetSymbolAddress((void**)&p_bsum,  g_bsum);
    float* p_gates = nullptr; cudaGetSymbolAddress((void**)&p_gates, g_gates);
    float* p_hW1h  = nullptr; cudaGetSymbolAddress((void**)&p_hW1h,  g_hW1h);
    float* p_pool  = nullptr; cudaGetSymbolAddress((void**)&p_pool,  g_pool);
    float* p_dcat  = nullptr; cudaGetSymbolAddress((void**)&p_dcat,  g_dcat);
    float* p_D1    = nullptr; cudaGetSymbolAddress((void**)&p_D1,    g_D1);
    __nv_bfloat16* p_embhi = nullptr; cudaGetSymbolAddress((void**)&p_embhi, g_embhi);
    __nv_bfloat16* p_emblo = nullptr; cudaGetSymbolAddress((void**)&p_emblo, g_emblo);
    __nv_bfloat16* p_W1ehi = nullptr; cudaGetSymbolAddress((void**)&p_W1ehi, g_W1ehi);
    __nv_bfloat16* p_W1elo = nullptr; cudaGetSymbolAddress((void**)&p_W1elo, g_W1elo);
    __nv_bfloat16* p_X1hi  = nullptr; cudaGetSymbolAddress((void**)&p_X1hi,  g_X1hi);
    __nv_bfloat16* p_X1lo  = nullptr; cudaGetSymbolAddress((void**)&p_X1lo,  g_X1lo);
    __nv_bfloat16* p_W2hi  = nullptr; cudaGetSymbolAddress((void**)&p_W2hi,  g_W2hi);
    __nv_bfloat16* p_W2lo  = nullptr; cudaGetSymbolAddress((void**)&p_W2lo,  g_W2lo);

    cudaFuncSetAttribute(hgemm<0>, cudaFuncAttributeMaxDynamicSharedMemorySize, HG_DYN);
    cudaFuncSetAttribute(hgemm<1>, cudaFuncAttributeMaxDynamicSharedMemorySize, HG_DYN);

    init_kernel<<<(BOTTLE*PRE + 255)/256, 256>>>(hh, ch, last_pos, last_pos_rel,
                                                 W_ih, W_hh, b_ih, b_hh, Wse, bse, W1, W2);

    for (int t = 0; t < SEQ_LEN; t++) {
        const float* gt = pred_traj_rel + t * BATCH * 2;
        float* out_pred = out + t * BATCH * 2;

        // LSTM cell
        pack_lstm_kernel<<<(BATCH*KCAT + 255)/256, 256>>>();
        sgemm64<1><<<dim3(GATES/64, BATCH/64), 256>>>(p_acat, KCAT, p_Wcat, KCAT,
                                                      p_gates, GATES, KCAT, p_bsum);
        lstm_elem_kernel<<<(BATCH*HD + 255)/256, 256>>>();

        // rel_pos / curr_pos / pred output / loss
        pos_loss_kernel<<<1, BATCH>>>(Wpos, bpos, gt, out_pred);

        // pool net
        emb_kernel<<<(ROWS_PN*ED + 255)/256, 256>>>(Wp, bp);
        sgemm64<0><<<dim3(PRE/64, BATCH/64), 256>>>(p_h, HD, W1 + ED, KCAT,
                                                    p_hW1h, PRE, HD, nullptr);
        // X1 = relu(emb @ W1e^T + hW1h[j] + b1) -> bf16 hi/lo (HMMA)
        hgemm<1><<<dim3(PRE/128, ROWS_PN/256), 256, HG_DYN>>>(
            p_embhi, p_emblo, p_W1ehi, p_W1elo, ED, ED, 1, b1, p_hW1h, nullptr);
        // pool = relu(max_j(X1 @ W2^T) + b2) (HMMA, register epilogue)
        hgemm<0><<<dim3(BOTTLE/128, ROWS_PN/256), 256, HG_DYN>>>(
            p_X1hi, p_X1lo, p_W2hi, p_W2lo, PRE, PRE, PRE/64, b2, nullptr, p_pool);

        // decoder MLP
        pack_dh_kernel<<<(BATCH*DHK + 255)/256, 256>>>();
        sgemm64<2><<<dim3(MLPD/64, BATCH/64), 256>>>(p_dcat, DHK, Wm1, DHK,
                                                     p_D1, MLPD, DHK, bm1);
        sgemm64<2><<<dim3(HD/64, BATCH/64), 256>>>(p_D1, MLPD, Wm2, MLPD,
                                                   p_h, HD, MLPD, bm2);

        decin_kernel<<<(BATCH*ED + 255)/256, 256>>>(gt, Wse, bse);
    }

    finish_kernel<<<1, 1>>>(out, out_size);
}